// round 16
// baseline (speedup 1.0000x reference)
#include <cuda_runtime.h>
#include <cuda_bf16.h>
#include <cuda_fp16.h>

// Problem constants
#define Bc  32
#define Nc  1024
#define Tc  64
#define Dc  32
#define NTc 1088   // N + T

__device__ float g_sa[Bc * Nc * Dc];
__device__ float g_tb[Bc * Nc * Dc];
__device__ float g_sb[Bc * Tc * Dc];
__device__ float g_ta[Bc * Tc * Dc];

// proj-done flag + consumer counter (reset by last consumer each launch)
__device__ int g_done = 0;
__device__ int g_consumed = 0;

__device__ __forceinline__ float tanh_ap(float x) {
    float y;
    asm("tanh.approx.f32 %0, %1;" : "=f"(y) : "f"(x));
    return y;
}
__device__ __forceinline__ float tanh_relu(float x) {
    return tanh_ap(fmaxf(x, 0.0f));
}
__device__ __forceinline__ __half2 tanh2_ap(__half2 x) {
    unsigned xi = *reinterpret_cast<unsigned*>(&x);
    unsigned yi;
    asm("tanh.approx.f16x2 %0, %1;" : "=r"(yi) : "r"(xi));
    return *reinterpret_cast<__half2*>(&yi);
}

__device__ __forceinline__ unsigned tf32_hi(float x) {
    unsigned h;
    asm("cvt.rna.tf32.f32 %0, %1;" : "=r"(h) : "f"(x));
    return h;
}

__device__ __forceinline__ void mma_tf32(float* c, const unsigned* a,
                                         unsigned b0, unsigned b1) {
    asm("mma.sync.aligned.m16n8k8.row.col.f32.tf32.tf32.f32 "
        "{%0,%1,%2,%3}, {%4,%5,%6,%7}, {%8,%9}, {%0,%1,%2,%3};"
        : "+f"(c[0]), "+f"(c[1]), "+f"(c[2]), "+f"(c[3])
        : "r"(a[0]), "r"(a[1]), "r"(a[2]), "r"(a[3]), "r"(b0), "r"(b1));
}

// ---------------------------------------------------------------------------
// Single fused kernel, 4656 blocks:
//   [0,272)        proj (4 row-tiles each) -> g_*, then signal g_done
//   [272,4624)     period-17: 9 gram (64x128 tiles, 2304) + 8 pair (2048)
//   [4624,4656)    gram BR (32)
// Gram: 64x128 tile per block (supertile halves; diag computed fully,
// off-diag mirrored). One fill phase (6 LDG.128/thread, MLP=6).
// ---------------------------------------------------------------------------
__global__ void __launch_bounds__(256, 5)
fused_kernel(const float* __restrict__ sp, const float* __restrict__ tp,
             const float* __restrict__ st_w1, const float* __restrict__ st_b1,
             const float* __restrict__ st_w2, const float* __restrict__ st_b2,
             const float* __restrict__ ts_w1, const float* __restrict__ ts_b1,
             const float* __restrict__ ts_w2, const float* __restrict__ ts_b2,
             float* __restrict__ out)
{
    __shared__ __align__(16) float sbuf[6912];   // 27.6 KB
    int idx = blockIdx.x;
    int tid = threadIdx.x;

    int g = -1, p = -1;
    if (idx < 272) {
        // ------------------------ proj blocks ------------------------------
        float* xs = sbuf;            // [32][33]
        float* wa = sbuf + 1056;     // [32][32]
        float* wb = sbuf + 2080;     // [32][32]

        int tile0 = idx * 4;
        bool is_sp = tile0 < 1024;   // 1024 spatial tiles, 64 temporal

        for (int i = tid; i < 1024; i += 256) {
            int k = i >> 5, dd = i & 31;
            if (is_sp) {
                wa[i] = st_w1[k * 32 + dd];
                wb[i] = ts_w1[(32 + k) * 32 + dd];
            } else {
                wa[i] = st_w1[(32 + k) * 32 + dd];
                wb[i] = ts_w1[k * 32 + dd];
            }
        }

        int d  = tid & 31;
        int ty = tid >> 5;
        float b1a = is_sp ? 0.f : st_b1[d];
        float b1b = is_sp ? 0.f : ts_b1[d];

        float* o1 = is_sp ? g_sa : g_sb;
        float* o2 = is_sp ? g_tb : g_ta;

        for (int j = 0; j < 4; ++j) {
            int gr0 = (tile0 + j) * 32;
            const float* src = is_sp ? (sp + (size_t)gr0 * Dc)
                                     : (tp + (size_t)(gr0 - Bc * Nc) * Dc);
            __syncthreads();
            for (int i = tid; i < 1024; i += 256)
                xs[(i >> 5) * 33 + (i & 31)] = src[i];
            __syncthreads();

            float acc1[4], acc2[4];
            #pragma unroll
            for (int rr = 0; rr < 4; ++rr) { acc1[rr] = b1a; acc2[rr] = b1b; }

            #pragma unroll 4
            for (int k = 0; k < 32; ++k) {
                float wav = wa[k * 32 + d];
                float wbv = wb[k * 32 + d];
                #pragma unroll
                for (int rr = 0; rr < 4; ++rr) {
                    float x = xs[(ty + 8 * rr) * 33 + k];
                    acc1[rr] = fmaf(x, wav, acc1[rr]);
                    acc2[rr] = fmaf(x, wbv, acc2[rr]);
                }
            }

            size_t base = is_sp ? (size_t)gr0 : (size_t)(gr0 - Bc * Nc);
            #pragma unroll
            for (int rr = 0; rr < 4; ++rr) {
                size_t rw = base + ty + 8 * rr;
                o1[rw * 32 + d] = 0.5f * acc1[rr];
                o2[rw * 32 + d] = 0.5f * acc2[rr];
            }
        }

        __syncthreads();
        if (tid == 0) {
            __threadfence();
            atomicAdd(&g_done, 1);
        }
        return;
    } else if (idx < 4624) {
        int u = idx - 272, q = u / 17, r = u % 17;
        if (r < 9) g = q * 9 + r;            // 0..2303
        else       p = q * 8 + (r - 9);      // 0..2047
    } else {
        // ------------------- gram BR: tanh(relu(T @ T^T)) -------------------
        int b = idx - 4624;
        float* ts_s = sbuf;   // [64][33]
        const float* tb = tp + (size_t)b * Tc * Dc;
        for (int i = tid; i < 2048; i += 256)
            ts_s[(i >> 5) * 33 + (i & 31)] = tb[i];
        __syncthreads();

        float* ob = out + (size_t)b * NTc * NTc;
        for (int it = 0; it < 16; ++it) {
            int e = tid + 256 * it;
            int i = e >> 6, j = e & 63;
            float acc = 0.f;
            #pragma unroll
            for (int k = 0; k < 32; ++k)
                acc = fmaf(ts_s[i * 33 + k], ts_s[j * 33 + k], acc);
            ob[(size_t)(Nc + i) * NTc + (Nc + j)] = tanh_relu(acc);
        }
        return;
    }

    if (g >= 0) {
        // ---- gram TL: tanh(relu(S @ S^T)), 64 rows x 128 cols, tf32 MMA ----
        // Supertile halves: t<16 diag (full, no mirror); t>=16 upper (mirror).
        int b = g / 72, t = g % 72;
        int r0, c0;
        bool mirror;
        if (t < 16) {
            int st = t >> 1;
            r0 = st * 128 + (t & 1) * 64;
            c0 = st * 128;
            mirror = false;
        } else {
            int o = t - 16;
            int u2 = o >> 1;            // 0..27 -> (R,C), R<C
            int R = 0, rem = u2;
            while (rem >= 7 - R) { rem -= 7 - R; ++R; }
            int C = R + 1 + rem;
            r0 = R * 128 + (o & 1) * 64;
            c0 = C * 128;
            mirror = true;
        }

        unsigned* As = reinterpret_cast<unsigned*>(sbuf);          // [64][36] tf32
        unsigned* Bs = reinterpret_cast<unsigned*>(sbuf) + 2304;   // [128][36]

        const float* Xb = sp + (size_t)b * Nc * Dc;
        // Single fill phase: As (2 v4/thread) + Bs (4 v4/thread), MLP=6.
        for (int i = tid; i < 512; i += 256) {
            int row = i >> 3, kq = i & 7;
            float4 v = *reinterpret_cast<const float4*>(
                Xb + (size_t)(r0 + row) * 32 + kq * 4);
            uint4 tv;
            tv.x = tf32_hi(v.x); tv.y = tf32_hi(v.y);
            tv.z = tf32_hi(v.z); tv.w = tf32_hi(v.w);
            *reinterpret_cast<uint4*>(As + row * 36 + kq * 4) = tv;
        }
        for (int i = tid; i < 1024; i += 256) {
            int row = i >> 3, kq = i & 7;
            float4 v = *reinterpret_cast<const float4*>(
                Xb + (size_t)(c0 + row) * 32 + kq * 4);
            uint4 tv;
            tv.x = tf32_hi(v.x); tv.y = tf32_hi(v.y);
            tv.z = tf32_hi(v.z); tv.w = tf32_hi(v.w);
            *reinterpret_cast<uint4*>(Bs + row * 36 + kq * 4) = tv;
        }
        __syncthreads();

        int w    = tid >> 5, lane = tid & 31;
        int wr   = w & 3;           // row quarter: rows 16wr..16wr+15
        int wcol = w >> 2;          // col sub-half within each 64-col group
        int gg   = lane >> 2;       // groupID 0..7
        int tig  = lane & 3;        // thread-in-group 0..3

        const unsigned* arow = As + (16 * wr + gg) * 36;

        float acc[2][4][4];         // [col group cg][nf][frag]
        #pragma unroll
        for (int cg = 0; cg < 2; ++cg)
            #pragma unroll
            for (int nf = 0; nf < 4; ++nf)
                #pragma unroll
                for (int e = 0; e < 4; ++e) acc[cg][nf][e] = 0.f;

        #pragma unroll
        for (int s = 0; s < 4; ++s) {
            int ks = 8 * s;
            unsigned ahi[4];
            ahi[0] = arow[ks + tig];
            ahi[1] = arow[8 * 36 + ks + tig];
            ahi[2] = arow[ks + tig + 4];
            ahi[3] = arow[8 * 36 + ks + tig + 4];

            #pragma unroll
            for (int cg = 0; cg < 2; ++cg) {
                #pragma unroll
                for (int nf = 0; nf < 4; ++nf) {
                    const unsigned* brow =
                        Bs + (64 * cg + 32 * wcol + 8 * nf + gg) * 36;
                    unsigned bh0 = brow[ks + tig];
                    unsigned bh1 = brow[ks + tig + 4];
                    mma_tf32(acc[cg][nf], ahi, bh0, bh1);
                }
            }
        }

        float* ob = out + (size_t)b * NTc * NTc;
        int rowA = r0 + 16 * wr + gg;
        int rl = 16 * wr + gg;
        int c_m  = tid >> 2;        // mirror writer: local col 0..63
        int qd = tid & 3;

        #pragma unroll
        for (int cg = 0; cg < 2; ++cg) {
            // activation + direct store
            #pragma unroll
            for (int nf = 0; nf < 4; ++nf) {
                #pragma unroll
                for (int e = 0; e < 4; ++e)
                    acc[cg][nf][e] = tanh_relu(acc[cg][nf][e]);
                int col = c0 + 64 * cg + 32 * wcol + 8 * nf + 2 * tig;
                float2 p0; p0.x = acc[cg][nf][0]; p0.y = acc[cg][nf][1];
                float2 p1; p1.x = acc[cg][nf][2]; p1.y = acc[cg][nf][3];
                *reinterpret_cast<float2*>(ob + (size_t)rowA * NTc + col) = p0;
                *reinterpret_cast<float2*>(ob + (size_t)(rowA + 8) * NTc + col) = p1;
            }
            if (mirror) {
                __syncthreads();          // As/Bs reads done (cg=0) / Ms reuse
                float* Ms = sbuf;         // [64][68]: Ms[col_local][row_local]
                #pragma unroll
                for (int nf = 0; nf < 4; ++nf) {
                    int cl = 32 * wcol + 8 * nf + 2 * tig;
                    Ms[(cl    ) * 68 + rl    ] = acc[cg][nf][0];
                    Ms[(cl + 1) * 68 + rl    ] = acc[cg][nf][1];
                    Ms[(cl    ) * 68 + rl + 8] = acc[cg][nf][2];
                    Ms[(cl + 1) * 68 + rl + 8] = acc[cg][nf][3];
                }
                __syncthreads();
                #pragma unroll
                for (int u = 0; u < 4; ++u) {
                    float4 v = *reinterpret_cast<float4*>(
                        Ms + c_m * 68 + qd * 16 + 4 * u);
                    *reinterpret_cast<float4*>(
                        ob + (size_t)(c0 + 64 * cg + c_m) * NTc + r0 + qd * 16 + 4 * u) = v;
                }
            }
        }
    } else {
        // ----------- bilinear MLP pair blocks: 32x64 tile, half2 math -------
        int RA, CB, ROFF, COFF, r0, c0, b;
        const float *Arow, *Bcol, *w2, *b2;
        if (p < 1024) {            // st: rows spatial, cols temporal
            b = p >> 5; r0 = (p & 31) * 32; c0 = 0;
            RA = Nc; CB = Tc; ROFF = 0; COFF = Nc;
            Arow = g_sa; Bcol = g_sb; w2 = st_w2; b2 = st_b2;
        } else {                   // ts: rows temporal, cols spatial
            int s2 = p - 1024;
            b = s2 >> 5;
            int sub = s2 & 31;
            r0 = (sub & 1) * 32; c0 = (sub >> 1) * 64;
            RA = Tc; CB = Nc; ROFF = Nc; COFF = 0;
            Arow = g_ta; Bcol = g_tb; w2 = ts_w2; b2 = ts_b2;
        }

        __half2* rsh = reinterpret_cast<__half2*>(sbuf);          // [32][18]
        __half2* csh = reinterpret_cast<__half2*>(sbuf) + 576;    // [64][17]
        float*   w2s = sbuf + 1664;                               // [32]
        __half2* w2h = reinterpret_cast<__half2*>(sbuf + 1696);   // [16]
        float*   wcp = sbuf + 1712;                               // [1]

        // w2/b2 are kernel inputs — load before the wait.
        if (tid < 32) w2s[tid] = w2[tid];

        // Wait for proj completion (proj blocks all wave-1 resident).
        if (tid == 0) {
            while (*((volatile int*)&g_done) < 272) { }
            __threadfence();
            int old = atomicAdd(&g_consumed, 1);
            if (old == 2047) {          // last passer resets for replay
                g_done = 0;
                g_consumed = 0;
                __threadfence();
            }
        }
        __syncthreads();

        // Fill in half2 (d-pairs).
        for (int i = tid; i < 512; i += 256) {       // rs: 32 rows x 16 h
            int row = i >> 4, h = i & 15;
            float2 v = *reinterpret_cast<const float2*>(
                Arow + ((size_t)b * RA + r0 + row) * 32 + h * 2);
            rsh[row * 18 + h] = __floats2half2_rn(v.x, v.y);
        }
        for (int i = tid; i < 1024; i += 256) {      // cs: 64 rows x 16 h
            int row = i >> 4, h = i & 15;
            float2 v = *reinterpret_cast<const float2*>(
                Bcol + ((size_t)b * CB + c0 + row) * 32 + h * 2);
            csh[row * 17 + h] = __floats2half2_rn(v.x, v.y);
        }
        __syncthreads();
        if (tid < 16)
            w2h[tid] = __floats2half2_rn(w2s[2 * tid], w2s[2 * tid + 1]);
        if (tid == 0) {
            float s = 0.f;
            #pragma unroll
            for (int d = 0; d < 32; ++d) s += w2s[d];
            wcp[0] = fmaf(0.5f, s, b2[0]);
        }
        __syncthreads();

        int tc = tid & 31;   // col pair: cols tc, tc+32
        int tr = tid >> 5;   // warp id: rows tr + 8k (warp-uniform -> bcast)

        const __half2* crow0 = csh + tc * 17;          // CF: 17tc+h distinct
        const __half2* crow1 = csh + (tc + 32) * 17;

        __half2 zero = __floats2half2_rn(0.f, 0.f);
        __half2 acc0[4][2], acc1[4][2];
        #pragma unroll
        for (int k = 0; k < 4; ++k)
            #pragma unroll
            for (int c = 0; c < 2; ++c) { acc0[k][c] = zero; acc1[k][c] = zero; }

        #pragma unroll
        for (int h = 0; h < 16; ++h) {
            __half2 cv0 = crow0[h];
            __half2 cv1 = crow1[h];
            __half2 wv  = w2h[h];
            #pragma unroll
            for (int k = 0; k < 4; ++k) {
                __half2 rv = rsh[(tr + 8 * k) * 18 + h];   // warp broadcast
                __half2 t0 = tanh2_ap(__hadd2(rv, cv0));
                __half2 t1 = tanh2_ap(__hadd2(rv, cv1));
                if (h < 8) {
                    acc0[k][0] = __hfma2(wv, t0, acc0[k][0]);
                    acc0[k][1] = __hfma2(wv, t1, acc0[k][1]);
                } else {
                    acc1[k][0] = __hfma2(wv, t0, acc1[k][0]);
                    acc1[k][1] = __hfma2(wv, t1, acc1[k][1]);
                }
            }
        }

        float wconst = wcp[0];
        float* ob = out + (size_t)b * NTc * NTc;
        #pragma unroll
        for (int k = 0; k < 4; ++k) {
            size_t rowbase = (size_t)(ROFF + r0 + tr + 8 * k) * NTc + COFF + c0;
            #pragma unroll
            for (int c = 0; c < 2; ++c) {
                float2 a0 = __half22float2(acc0[k][c]);
                float2 a1 = __half22float2(acc1[k][c]);
                float accf = (a0.x + a0.y) + (a1.x + a1.y);
                ob[rowbase + tc + 32 * c] = tanh_relu(fmaf(0.5f, accf, wconst));
            }
        }
    }
}

// ---------------------------------------------------------------------------
extern "C" void kernel_launch(void* const* d_in, const int* in_sizes, int n_in,
                              void* d_out, int out_size)
{
    const float* sp    = (const float*)d_in[0];
    const float* tp    = (const float*)d_in[1];
    const float* st_w1 = (const float*)d_in[2];
    const float* st_b1 = (const float*)d_in[3];
    const float* st_w2 = (const float*)d_in[4];
    const float* st_b2 = (const float*)d_in[5];
    const float* ts_w1 = (const float*)d_in[6];
    const float* ts_b1 = (const float*)d_in[7];
    const float* ts_w2 = (const float*)d_in[8];
    const float* ts_b2 = (const float*)d_in[9];
    float* out = (float*)d_out;

    fused_kernel<<<4656, 256>>>(sp, tp, st_w1, st_b1, st_w2, st_b2,
                                ts_w1, ts_b1, ts_w2, ts_b2, out);
}

// round 17
// speedup vs baseline: 1.0260x; 1.0260x over previous
#include <cuda_runtime.h>
#include <cuda_bf16.h>
#include <cuda_fp16.h>

// Problem constants
#define Bc  32
#define Nc  1024
#define Tc  64
#define Dc  32
#define NTc 1088   // N + T

// Projections stored as HALF (rounded once in proj — bit-identical to the
// former fp32-store + half-convert-at-pair-fill path).
__device__ __half g_sa[Bc * Nc * Dc];
__device__ __half g_tb[Bc * Nc * Dc];
__device__ __half g_sb[Bc * Tc * Dc];
__device__ __half g_ta[Bc * Tc * Dc];

// proj-done flag + consumer counter (reset by last consumer each launch)
__device__ int g_done = 0;
__device__ int g_consumed = 0;

__device__ __forceinline__ float tanh_ap(float x) {
    float y;
    asm("tanh.approx.f32 %0, %1;" : "=f"(y) : "f"(x));
    return y;
}
__device__ __forceinline__ float tanh_relu(float x) {
    return tanh_ap(fmaxf(x, 0.0f));
}
__device__ __forceinline__ __half2 tanh2_ap(__half2 x) {
    unsigned xi = *reinterpret_cast<unsigned*>(&x);
    unsigned yi;
    asm("tanh.approx.f16x2 %0, %1;" : "=r"(yi) : "r"(xi));
    return *reinterpret_cast<__half2*>(&yi);
}

__device__ __forceinline__ unsigned tf32_hi(float x) {
    unsigned h;
    asm("cvt.rna.tf32.f32 %0, %1;" : "=r"(h) : "f"(x));
    return h;
}

__device__ __forceinline__ void mma_tf32(float* c, const unsigned* a,
                                         unsigned b0, unsigned b1) {
    asm("mma.sync.aligned.m16n8k8.row.col.f32.tf32.tf32.f32 "
        "{%0,%1,%2,%3}, {%4,%5,%6,%7}, {%8,%9}, {%0,%1,%2,%3};"
        : "+f"(c[0]), "+f"(c[1]), "+f"(c[2]), "+f"(c[3])
        : "r"(a[0]), "r"(a[1]), "r"(a[2]), "r"(a[3]), "r"(b0), "r"(b1));
}

// ---------------------------------------------------------------------------
// Single fused kernel, 6704 blocks (R14 layout):
//   [0,272)        proj (4 row-tiles each) -> g_* (half), then signal g_done
//   [272,740)      gram (wave-1 filler; no dependency)
//   [740,6628)     period-23: 15 gram + 8 pair
//   [6628,6672)    gram tail (44)
//   [6672,6704)    gram BR (32)
// ---------------------------------------------------------------------------
__global__ void __launch_bounds__(256, 5)
fused_kernel(const float* __restrict__ sp, const float* __restrict__ tp,
             const float* __restrict__ st_w1, const float* __restrict__ st_b1,
             const float* __restrict__ st_w2, const float* __restrict__ st_b2,
             const float* __restrict__ ts_w1, const float* __restrict__ ts_b1,
             const float* __restrict__ ts_w2, const float* __restrict__ ts_b2,
             float* __restrict__ out)
{
    __shared__ __align__(16) float sbuf[4800];   // 19.2 KB
    int idx = blockIdx.x;
    int tid = threadIdx.x;

    int g = -1, p = -1;
    if (idx < 272) {
        // ------------------------ proj blocks ------------------------------
        float* xs = sbuf;            // [32][33]
        float* wa = sbuf + 1056;     // [32][32]
        float* wb = sbuf + 2080;     // [32][32]

        int tile0 = idx * 4;
        bool is_sp = tile0 < 1024;   // 1024 spatial tiles, 64 temporal

        for (int i = tid; i < 1024; i += 256) {
            int k = i >> 5, dd = i & 31;
            if (is_sp) {
                wa[i] = st_w1[k * 32 + dd];
                wb[i] = ts_w1[(32 + k) * 32 + dd];
            } else {
                wa[i] = st_w1[(32 + k) * 32 + dd];
                wb[i] = ts_w1[k * 32 + dd];
            }
        }

        int d  = tid & 31;
        int ty = tid >> 5;
        float b1a = is_sp ? 0.f : st_b1[d];
        float b1b = is_sp ? 0.f : ts_b1[d];

        __half* o1 = is_sp ? g_sa : g_sb;
        __half* o2 = is_sp ? g_tb : g_ta;

        for (int j = 0; j < 4; ++j) {
            int gr0 = (tile0 + j) * 32;
            const float* src = is_sp ? (sp + (size_t)gr0 * Dc)
                                     : (tp + (size_t)(gr0 - Bc * Nc) * Dc);
            __syncthreads();
            for (int i = tid; i < 1024; i += 256)
                xs[(i >> 5) * 33 + (i & 31)] = src[i];
            __syncthreads();

            float acc1[4], acc2[4];
            #pragma unroll
            for (int rr = 0; rr < 4; ++rr) { acc1[rr] = b1a; acc2[rr] = b1b; }

            #pragma unroll 4
            for (int k = 0; k < 32; ++k) {
                float wav = wa[k * 32 + d];
                float wbv = wb[k * 32 + d];
                #pragma unroll
                for (int rr = 0; rr < 4; ++rr) {
                    float x = xs[(ty + 8 * rr) * 33 + k];
                    acc1[rr] = fmaf(x, wav, acc1[rr]);
                    acc2[rr] = fmaf(x, wbv, acc2[rr]);
                }
            }

            size_t base = is_sp ? (size_t)gr0 : (size_t)(gr0 - Bc * Nc);
            #pragma unroll
            for (int rr = 0; rr < 4; ++rr) {
                size_t rw = base + ty + 8 * rr;
                o1[rw * 32 + d] = __float2half_rn(0.5f * acc1[rr]);
                o2[rw * 32 + d] = __float2half_rn(0.5f * acc2[rr]);
            }
        }

        __syncthreads();
        if (tid == 0) {
            __threadfence();
            atomicAdd(&g_done, 1);
        }
        return;
    } else if (idx < 740) {
        g = idx - 272;                       // 0..467
    } else if (idx < 6628) {
        int u = idx - 740, q = u / 23, r = u % 23;
        if (r < 15) g = 468 + q * 15 + r;    // 468..4307
        else        p = q * 8 + (r - 15);    // 0..2047
    } else if (idx < 6672) {
        g = 4308 + (idx - 6628);             // 4308..4351
    } else {
        // ------------------- gram BR: tanh(relu(T @ T^T)) -------------------
        int b = idx - 6672;
        float* ts_s = sbuf;   // [64][33]
        const float* tb = tp + (size_t)b * Tc * Dc;
        for (int i = tid; i < 2048; i += 256)
            ts_s[(i >> 5) * 33 + (i & 31)] = tb[i];
        __syncthreads();

        float* ob = out + (size_t)b * NTc * NTc;
        for (int it = 0; it < 16; ++it) {
            int e = tid + 256 * it;
            int i = e >> 6, j = e & 63;
            float acc = 0.f;
            #pragma unroll
            for (int k = 0; k < 32; ++k)
                acc = fmaf(ts_s[i * 33 + k], ts_s[j * 33 + k], acc);
            ob[(size_t)(Nc + i) * NTc + (Nc + j)] = tanh_relu(acc);
        }
        return;
    }

    if (g >= 0) {
        // -------- gram TL: tanh(relu(S @ S^T)), 64x64 tile, tf32 MMA --------
        int b = g / 136, t = g % 136;
        int R = 0, rem = t;
        while (rem >= 16 - R) { rem -= 16 - R; ++R; }
        int C = R + rem;
        int r0 = R * 64, c0 = C * 64;
        bool mirror = (C > R);

        unsigned* As = reinterpret_cast<unsigned*>(sbuf);          // [64][36] tf32
        unsigned* Bs = reinterpret_cast<unsigned*>(sbuf) + 2304;   // [64][36]
        unsigned* BsP = mirror ? Bs : As;

        const float* Xb = sp + (size_t)b * Nc * Dc;
        for (int i = tid; i < 512; i += 256) {
            int row = i >> 3, kq = i & 7;
            float4 v = *reinterpret_cast<const float4*>(
                Xb + (size_t)(r0 + row) * 32 + kq * 4);
            uint4 tv;
            tv.x = tf32_hi(v.x); tv.y = tf32_hi(v.y);
            tv.z = tf32_hi(v.z); tv.w = tf32_hi(v.w);
            *reinterpret_cast<uint4*>(As + row * 36 + kq * 4) = tv;
        }
        if (mirror) {
            for (int i = tid; i < 512; i += 256) {
                int row = i >> 3, kq = i & 7;
                float4 v = *reinterpret_cast<const float4*>(
                    Xb + (size_t)(c0 + row) * 32 + kq * 4);
                uint4 tv;
                tv.x = tf32_hi(v.x); tv.y = tf32_hi(v.y);
                tv.z = tf32_hi(v.z); tv.w = tf32_hi(v.w);
                *reinterpret_cast<uint4*>(Bs + row * 36 + kq * 4) = tv;
            }
        }
        __syncthreads();

        int w    = tid >> 5, lane = tid & 31;
        int wr   = w & 3;           // row quarter: rows 16wr..16wr+15
        int wcol = w >> 2;          // col half: cols 32wcol..+31
        int gg   = lane >> 2;       // groupID 0..7
        int tig  = lane & 3;        // thread-in-group 0..3

        const unsigned* arow = As + (16 * wr + gg) * 36;

        float acc[4][4];
        #pragma unroll
        for (int nf = 0; nf < 4; ++nf)
            #pragma unroll
            for (int e = 0; e < 4; ++e) acc[nf][e] = 0.f;

        #pragma unroll
        for (int s = 0; s < 4; ++s) {
            int ks = 8 * s;
            unsigned ahi[4];
            ahi[0] = arow[ks + tig];
            ahi[1] = arow[8 * 36 + ks + tig];
            ahi[2] = arow[ks + tig + 4];
            ahi[3] = arow[8 * 36 + ks + tig + 4];

            #pragma unroll
            for (int nf = 0; nf < 4; ++nf) {
                const unsigned* brow = BsP + (32 * wcol + 8 * nf + gg) * 36;
                unsigned bh0 = brow[ks + tig];
                unsigned bh1 = brow[ks + tig + 4];
                mma_tf32(acc[nf], ahi, bh0, bh1);
            }
        }

        float* ob = out + (size_t)b * NTc * NTc;
        int rowA = r0 + 16 * wr + gg;
        #pragma unroll
        for (int nf = 0; nf < 4; ++nf) {
            #pragma unroll
            for (int e = 0; e < 4; ++e) acc[nf][e] = tanh_relu(acc[nf][e]);
            int col = c0 + 32 * wcol + 8 * nf + 2 * tig;
            float2 p0; p0.x = acc[nf][0]; p0.y = acc[nf][1];
            float2 p1; p1.x = acc[nf][2]; p1.y = acc[nf][3];
            *reinterpret_cast<float2*>(ob + (size_t)rowA * NTc + col) = p0;
            *reinterpret_cast<float2*>(ob + (size_t)(rowA + 8) * NTc + col) = p1;
        }

        if (mirror) {
            __syncthreads();          // all warps done reading As/Bs
            float* Ms = sbuf;         // [64][68]: Ms[col_local][row_local]
            int rl = 16 * wr + gg;
            #pragma unroll
            for (int nf = 0; nf < 4; ++nf) {
                int cl = 32 * wcol + 8 * nf + 2 * tig;
                Ms[(cl    ) * 68 + rl    ] = acc[nf][0];
                Ms[(cl + 1) * 68 + rl    ] = acc[nf][1];
                Ms[(cl    ) * 68 + rl + 8] = acc[nf][2];
                Ms[(cl + 1) * 68 + rl + 8] = acc[nf][3];
            }
            __syncthreads();
            int c  = tid >> 2;        // 0..63 (mirror row = original col)
            int qd = tid & 3;
            #pragma unroll
            for (int u = 0; u < 4; ++u) {
                float4 v = *reinterpret_cast<float4*>(Ms + c * 68 + qd * 16 + 4 * u);
                *reinterpret_cast<float4*>(
                    ob + (size_t)(c0 + c) * NTc + r0 + qd * 16 + 4 * u) = v;
            }
        }
    } else {
        // ----------- bilinear MLP pair blocks: 32x64 tile, half2 math -------
        int RA, CB, ROFF, COFF, r0, c0, b;
        const __half *Arow, *Bcol;
        const float *w2, *b2;
        if (p < 1024) {            // st: rows spatial, cols temporal
            b = p >> 5; r0 = (p & 31) * 32; c0 = 0;
            RA = Nc; CB = Tc; ROFF = 0; COFF = Nc;
            Arow = g_sa; Bcol = g_sb; w2 = st_w2; b2 = st_b2;
        } else {                   // ts: rows temporal, cols spatial
            int s2 = p - 1024;
            b = s2 >> 5;
            int sub = s2 & 31;
            r0 = (sub & 1) * 32; c0 = (sub >> 1) * 64;
            RA = Tc; CB = Nc; ROFF = Nc; COFF = 0;
            Arow = g_ta; Bcol = g_tb; w2 = ts_w2; b2 = ts_b2;
        }

        __half2* rsh = reinterpret_cast<__half2*>(sbuf);          // [32][18]
        __half2* csh = reinterpret_cast<__half2*>(sbuf) + 576;    // [64][17]
        float*   w2s = sbuf + 1664;                               // [32]
        __half2* w2h = reinterpret_cast<__half2*>(sbuf + 1696);   // [16]
        float*   wcp = sbuf + 1712;                               // [1]

        // w2/b2 are kernel inputs — load before the wait.
        if (tid < 32) w2s[tid] = w2[tid];

        // Wait for proj completion.
        if (tid == 0) {
            while (*((volatile int*)&g_done) < 272) { }
            __threadfence();
            int old = atomicAdd(&g_consumed, 1);
            if (old == 2047) {          // last passer resets for replay
                g_done = 0;
                g_consumed = 0;
                __threadfence();
            }
        }
        __syncthreads();

        // Fill (g_* already half2-packed: direct copies, no conversion).
        const __half2* Ah2 = reinterpret_cast<const __half2*>(Arow);
        const __half2* Bh2 = reinterpret_cast<const __half2*>(Bcol);
        for (int i = tid; i < 512; i += 256) {       // rs: 32 rows x 16 h
            int row = i >> 4, h = i & 15;
            rsh[row * 18 + h] = Ah2[((size_t)b * RA + r0 + row) * 16 + h];
        }
        for (int i = tid; i < 1024; i += 256) {      // cs: 64 rows x 16 h
            int row = i >> 4, h = i & 15;
            csh[row * 17 + h] = Bh2[((size_t)b * CB + c0 + row) * 16 + h];
        }
        __syncthreads();
        if (tid < 16)
            w2h[tid] = __floats2half2_rn(w2s[2 * tid], w2s[2 * tid + 1]);
        if (tid == 0) {
            float s = 0.f;
            #pragma unroll
            for (int d = 0; d < 32; ++d) s += w2s[d];
            wcp[0] = fmaf(0.5f, s, b2[0]);
        }
        __syncthreads();

        int tc = tid & 63;
        int tr = tid >> 6;

        const __half2* crow = csh + tc * 17;   // bank = (17tc+h) mod 32: CF

        __half2 zero = __floats2half2_rn(0.f, 0.f);
        __half2 acc0[8], acc1[8];
        #pragma unroll
        for (int ii = 0; ii < 8; ++ii) { acc0[ii] = zero; acc1[ii] = zero; }

        #pragma unroll
        for (int h = 0; h < 16; ++h) {
            __half2 cv = crow[h];
            __half2 wv = w2h[h];
            #pragma unroll
            for (int ii = 0; ii < 8; ++ii) {
                __half2 rv = rsh[(tr + 4 * ii) * 18 + h];   // broadcast
                __half2 t  = tanh2_ap(__hadd2(rv, cv));
                if (h < 8) acc0[ii] = __hfma2(wv, t, acc0[ii]);
                else       acc1[ii] = __hfma2(wv, t, acc1[ii]);
            }
        }

        float wconst = wcp[0];
        float* ob = out + (size_t)b * NTc * NTc;
        #pragma unroll
        for (int ii = 0; ii < 8; ++ii) {
            float2 a0 = __half22float2(acc0[ii]);
            float2 a1 = __half22float2(acc1[ii]);
            float accf = (a0.x + a0.y) + (a1.x + a1.y);
            ob[(size_t)(ROFF + r0 + tr + 4 * ii) * NTc + (COFF + c0 + tc)]
                = tanh_relu(fmaf(0.5f, accf, wconst));
        }
    }
}

// ---------------------------------------------------------------------------
extern "C" void kernel_launch(void* const* d_in, const int* in_sizes, int n_in,
                              void* d_out, int out_size)
{
    const float* sp    = (const float*)d_in[0];
    const float* tp    = (const float*)d_in[1];
    const float* st_w1 = (const float*)d_in[2];
    const float* st_b1 = (const float*)d_in[3];
    const float* st_w2 = (const float*)d_in[4];
    const float* st_b2 = (const float*)d_in[5];
    const float* ts_w1 = (const float*)d_in[6];
    const float* ts_b1 = (const float*)d_in[7];
    const float* ts_w2 = (const float*)d_in[8];
    const float* ts_b2 = (const float*)d_in[9];
    float* out = (float*)d_out;

    fused_kernel<<<6704, 256>>>(sp, tp, st_w1, st_b1, st_w2, st_b2,
                                ts_w1, ts_b1, ts_w2, ts_b2, out);
}